// round 10
// baseline (speedup 1.0000x reference)
#include <cuda_runtime.h>
#include <cuda_bf16.h>
#include <cstdint>

typedef unsigned long long ull;
typedef unsigned int       u32;
typedef unsigned short     u16;

#define RR 10

// Split bilinear-form matrices W[u][k], k = a*16 + a2, bf16 hi/lo parts.
__device__ u16 Whi_g[32 * 256];
__device__ u16 Wlo_g[32 * 256];
__device__ u32 g_ticket;

// ---------------------------------------------------------------------------
// Precompute kernel: one block per unit u. Builds W[u][k]=S[u][a][a2], split bf16.
// ---------------------------------------------------------------------------
__global__ void precompute_S(const float* __restrict__ core11,
                             const float* __restrict__ core12,
                             const float* __restrict__ core13,
                             const float* __restrict__ core14,
                             const float* __restrict__ core21,
                             const float* __restrict__ core22,
                             const float* __restrict__ FM,   // [2][10][8][32]
                             const float* __restrict__ MT)   // [10][10]
{
    __shared__ float v[8][2][RR];
    __shared__ float WP[4][2][RR][RR];
    __shared__ float P[4][4][RR];
    __shared__ float W2[2][4][RR][RR];
    __shared__ float Q[2][16][RR];
    __shared__ float QT[16][RR];

    const int u = blockIdx.x;
    const int tid = threadIdx.x;

    if (u == 0 && tid == 0) g_ticket = 0u;   // reset warp ticket for tree_main

    for (int idx = tid; idx < 8 * 2 * RR; idx += blockDim.x) {
        int f = idx / (2 * RR);
        int d = (idx / RR) & 1;
        int r = idx % RR;
        v[f][d][r] = FM[((d * RR + r) * 8 + f) * 32 + u];
    }
    __syncthreads();

    const float* cores1[4] = {core11, core12, core13, core14};

    for (int idx = tid; idx < 800; idx += blockDim.x) {
        int p  = idx / 200;
        int al = (idx / 100) & 1;
        int k  = (idx / RR) % RR;
        int j  = idx % RR;
        const float* core = cores1[p];
        float s = 0.f;
        #pragma unroll
        for (int i = 0; i < RR; i++)
            s += v[2 * p][al][i] * __ldg(&core[(i * RR + k) * RR + j]);
        WP[p][al][k][j] = s;
    }
    __syncthreads();

    for (int idx = tid; idx < 160; idx += blockDim.x) {
        int p = idx / 40;
        int c = (idx / RR) & 3;
        int j = idx % RR;
        int al = c >> 1, be = c & 1;
        float s = 0.f;
        #pragma unroll
        for (int k = 0; k < RR; k++)
            s += v[2 * p + 1][be][k] * WP[p][al][k][j];
        P[p][c][j] = s;
    }
    __syncthreads();

    for (int idx = tid; idx < 800; idx += blockDim.x) {
        int t  = idx / 400;
        int c1 = (idx / 100) & 3;
        int k  = (idx / RR) % RR;
        int j  = idx % RR;
        const float* core = t ? core22 : core21;
        float s = 0.f;
        #pragma unroll
        for (int i = 0; i < RR; i++)
            s += P[2 * t][c1][i] * __ldg(&core[(i * RR + k) * RR + j]);
        W2[t][c1][k][j] = s;
    }
    __syncthreads();

    for (int idx = tid; idx < 320; idx += blockDim.x) {
        int t = idx / 160;
        int a = (idx / RR) % 16;
        int j = idx % RR;
        int c1 = a >> 2, c2 = a & 3;
        float s = 0.f;
        #pragma unroll
        for (int k = 0; k < RR; k++)
            s += P[2 * t + 1][c2][k] * W2[t][c1][k][j];
        Q[t][a][j] = s;
    }
    __syncthreads();

    for (int idx = tid; idx < 160; idx += blockDim.x) {
        int a = idx / RR, j = idx % RR;
        float s = 0.f;
        #pragma unroll
        for (int i = 0; i < RR; i++)
            s += Q[0][a][i] * __ldg(&MT[i * RR + j]);
        QT[a][j] = s;
    }
    __syncthreads();

    for (int idx = tid; idx < 256; idx += blockDim.x) {
        int a = idx >> 4, a2 = idx & 15;
        float s = 0.f;
        #pragma unroll
        for (int j = 0; j < RR; j++)
            s += QT[a][j] * Q[1][a2][j];
        // split: hi = truncate-to-bf16 (exact), lo = rn-bf16 of residual
        u32 bits = __float_as_uint(s);
        float hif = __uint_as_float(bits & 0xFFFF0000u);
        __nv_bfloat16 lo = __float2bfloat16(s - hif);
        int k = a * 16 + a2;
        Whi_g[u * 256 + k] = (u16)(bits >> 16);
        Wlo_g[u * 256 + k] = *reinterpret_cast<u16*>(&lo);
    }
}

// ---------------------------------------------------------------------------
// Warp-MMA helpers (arch-agnostic: sm_80+ mma.sync)
// ---------------------------------------------------------------------------
__device__ __forceinline__ void mma_bf16(float* d, const u32* a, u32 b0, u32 b1) {
    asm volatile("mma.sync.aligned.m16n8k16.row.col.f32.bf16.bf16.f32 "
                 "{%0,%1,%2,%3}, {%4,%5,%6,%7}, {%8,%9}, {%0,%1,%2,%3};"
                 : "+f"(d[0]), "+f"(d[1]), "+f"(d[2]), "+f"(d[3])
                 : "r"(a[0]), "r"(a[1]), "r"(a[2]), "r"(a[3]), "r"(b0), "r"(b1));
}
__device__ __forceinline__ u32 pack_hi(float z0, float z1) {
    u32 r;
    asm("prmt.b32 %0, %1, %2, 0x7632;"
        : "=r"(r) : "r"(__float_as_uint(z0)), "r"(__float_as_uint(z1)));
    return r;
}
__device__ __forceinline__ u32 pack_lo_rn(float l0, float l1) {
    u32 r;
    asm("cvt.rn.bf16x2.f32 %0, %1, %2;" : "=r"(r) : "f"(l1), "f"(l0));
    return r;
}
__device__ __forceinline__ float trunc_bf(float z) {
    return __uint_as_float(__float_as_uint(z) & 0xFFFF0000u);
}

// ---------------------------------------------------------------------------
// Main kernel: out = z @ W, A-fragments built in registers, per-warp dynamic
// tickets over 16-batch micro-tiles. Persistent 444 blocks (3/SM) x 256 thr.
// Next ticket is fetched BEFORE the MMA mainloop so the atomic latency is
// hidden under the 16 k-steps.
// ---------------------------------------------------------------------------
__global__ __launch_bounds__(256, 3) void tree_main(const float* __restrict__ X,
                                                    float* __restrict__ out,
                                                    int ntiles)
{
    __shared__ __align__(16) ulonglong2 sB[2048];   // 32KB: [ks][n][lane] = {bh, bl}

    const int tid  = threadIdx.x;
    const int lane = tid & 31;
    const int g    = lane >> 2;   // fragment row group (0..7)
    const int tig  = lane & 3;    // thread-in-group

    // ---- stage fused B fragments (validated per-lane layout) ----
    for (int e = tid; e < 2048; e += 256) {
        int l   = e & 31;
        int n   = (e >> 5) & 3;
        int ks  = e >> 7;
        int col = n * 8 + (l >> 2);
        int k0  = ks * 16 + (l & 3) * 2;
        const u16* wh = &Whi_g[col * 256];
        const u16* wl = &Wlo_g[col * 256];
        ull bh = (ull)wh[k0] | ((ull)wh[k0 + 1] << 16)
               | ((ull)wh[k0 + 8] << 32) | ((ull)wh[k0 + 9] << 48);
        ull bl = (ull)wl[k0] | ((ull)wl[k0 + 1] << 16)
               | ((ull)wl[k0 + 8] << 32) | ((ull)wl[k0 + 9] << 48);
        ulonglong2 p; p.x = bh; p.y = bl;
        sB[e] = p;
    }
    __syncthreads();

    // ---- per-warp ticket loop over 16-batch micro-tiles ----
    u32 tk;
    if (lane == 0) tk = atomicAdd(&g_ticket, 1u);
    tk = __shfl_sync(0xFFFFFFFFu, tk, 0);

    while (tk < (u32)ntiles) {
        const int base_b = (int)tk * 16;

        // monomial factors for this lane's two fragment rows (g, g+8):
        float a01r[2][4], a23r[2][4], m2r[2][4];
        #pragma unroll
        for (int r = 0; r < 2; r++) {
            int brow = base_b + g + r * 8;
            const float4* xp = reinterpret_cast<const float4*>(X + (size_t)brow * 16);
            float4 x0 = xp[0], x1 = xp[1], x2 = xp[2], x3 = xp[3];

            a01r[r][0]=x0.x*x0.z; a01r[r][1]=x0.x*x0.w;
            a01r[r][2]=x0.y*x0.z; a01r[r][3]=x0.y*x0.w;
            a23r[r][0]=x1.x*x1.z; a23r[r][1]=x1.x*x1.w;
            a23r[r][2]=x1.y*x1.z; a23r[r][3]=x1.y*x1.w;

            float a45[4], a67[4];
            a45[0]=x2.x*x2.z; a45[1]=x2.x*x2.w; a45[2]=x2.y*x2.z; a45[3]=x2.y*x2.w;
            a67[0]=x3.x*x3.z; a67[1]=x3.x*x3.w; a67[2]=x3.y*x3.z; a67[3]=x3.y*x3.w;

            #pragma unroll
            for (int j = 0; j < 4; j++) {
                int a2 = 2 * tig + (j >> 1) * 8 + (j & 1);
                m2r[r][j] = a45[a2 >> 2] * a67[a2 & 3];
            }
        }

        // fetch NEXT ticket now — atomic+shfl latency hides under the mainloop
        u32 tk_next;
        if (lane == 0) tk_next = atomicAdd(&g_ticket, 1u);
        tk_next = __shfl_sync(0xFFFFFFFFu, tk_next, 0);

        float acc[4][4];
        #pragma unroll
        for (int n = 0; n < 4; n++)
            #pragma unroll
            for (int i = 0; i < 4; i++) acc[n][i] = 0.f;

        // ---- 16 K-chunks (each = one 'a' index) ----
        #pragma unroll
        for (int ks = 0; ks < 16; ks++) {
            float m10 = a01r[0][ks >> 2] * a23r[0][ks & 3];
            float m11 = a01r[1][ks >> 2] * a23r[1][ks & 3];

            float z00 = m10 * m2r[0][0], z01 = m10 * m2r[0][1];
            float z02 = m10 * m2r[0][2], z03 = m10 * m2r[0][3];
            float z10 = m11 * m2r[1][0], z11 = m11 * m2r[1][1];
            float z12 = m11 * m2r[1][2], z13 = m11 * m2r[1][3];

            u32 ah[4], al_[4];
            ah[0] = pack_hi(z00, z01);
            ah[1] = pack_hi(z10, z11);
            ah[2] = pack_hi(z02, z03);
            ah[3] = pack_hi(z12, z13);
            al_[0] = pack_lo_rn(z00 - trunc_bf(z00), z01 - trunc_bf(z01));
            al_[1] = pack_lo_rn(z10 - trunc_bf(z10), z11 - trunc_bf(z11));
            al_[2] = pack_lo_rn(z02 - trunc_bf(z02), z03 - trunc_bf(z03));
            al_[3] = pack_lo_rn(z12 - trunc_bf(z12), z13 - trunc_bf(z13));

            u32 bh0[4], bh1[4], bl0[4], bl1[4];
            #pragma unroll
            for (int n = 0; n < 4; n++) {
                ulonglong2 bp = sB[(ks * 4 + n) * 32 + lane];   // one LDS.128
                bh0[n] = (u32)bp.x; bh1[n] = (u32)(bp.x >> 32);
                bl0[n] = (u32)bp.y; bl1[n] = (u32)(bp.y >> 32);
            }

            #pragma unroll
            for (int n = 0; n < 4; n++) mma_bf16(acc[n], ah,  bh0[n], bh1[n]);
            #pragma unroll
            for (int n = 0; n < 4; n++) mma_bf16(acc[n], ah,  bl0[n], bl1[n]);
            #pragma unroll
            for (int n = 0; n < 4; n++) mma_bf16(acc[n], al_, bh0[n], bh1[n]);
        }

        // ---- epilogue: D frag rows g/g+8, cols n*8 + tig*2, +1 ----
        #pragma unroll
        for (int n = 0; n < 4; n++) {
            float2 v0; v0.x = acc[n][0]; v0.y = acc[n][1];
            float2 v1; v1.x = acc[n][2]; v1.y = acc[n][3];
            *reinterpret_cast<float2*>(out + (size_t)(base_b + g)     * 32 + n * 8 + tig * 2) = v0;
            *reinterpret_cast<float2*>(out + (size_t)(base_b + g + 8) * 32 + n * 8 + tig * 2) = v1;
        }

        tk = tk_next;
    }
}

// ---------------------------------------------------------------------------
extern "C" void kernel_launch(void* const* d_in, const int* in_sizes, int n_in,
                              void* d_out, int out_size)
{
    const float* X   = (const float*)d_in[0];
    const float* c11 = (const float*)d_in[1];
    const float* c12 = (const float*)d_in[2];
    const float* c13 = (const float*)d_in[3];
    const float* c14 = (const float*)d_in[4];
    const float* c21 = (const float*)d_in[5];
    const float* c22 = (const float*)d_in[6];
    const float* FM  = (const float*)d_in[7];
    const float* MT  = (const float*)d_in[8];
    (void)n_in; (void)out_size;

    int B = in_sizes[0] / 16;          // X is [B, 8, 2]
    int ntiles = B / 16;               // 4096 16-batch micro-tiles

    precompute_S<<<32, 256>>>(c11, c12, c13, c14, c21, c22, FM, MT);
    tree_main<<<444, 256>>>(X, (float*)d_out, ntiles);
}

// round 11
// speedup vs baseline: 1.0727x; 1.0727x over previous
#include <cuda_runtime.h>
#include <cuda_bf16.h>
#include <cstdint>

typedef unsigned long long ull;
typedef unsigned int       u32;
typedef unsigned short     u16;

#define RR 10

// Pre-packed fused B fragments: e = ks*128 + n*32 + lane -> {bh, bl}
__device__ __align__(16) ulonglong2 Wpk_g[2048];

// ---------------------------------------------------------------------------
// Precompute kernel: one block per unit u. Builds S_u, splits to bf16 hi/lo,
// and writes the 64 fragment-packed entries this unit contributes.
// ---------------------------------------------------------------------------
__global__ void precompute_S(const float* __restrict__ core11,
                             const float* __restrict__ core12,
                             const float* __restrict__ core13,
                             const float* __restrict__ core14,
                             const float* __restrict__ core21,
                             const float* __restrict__ core22,
                             const float* __restrict__ FM,   // [2][10][8][32]
                             const float* __restrict__ MT)   // [10][10]
{
    __shared__ float v[8][2][RR];
    __shared__ float WP[4][2][RR][RR];
    __shared__ float P[4][4][RR];
    __shared__ float W2[2][4][RR][RR];
    __shared__ float Q[2][16][RR];
    __shared__ float QT[16][RR];
    __shared__ float Sv[256];

    const int u = blockIdx.x;
    const int tid = threadIdx.x;

    for (int idx = tid; idx < 8 * 2 * RR; idx += blockDim.x) {
        int f = idx / (2 * RR);
        int d = (idx / RR) & 1;
        int r = idx % RR;
        v[f][d][r] = FM[((d * RR + r) * 8 + f) * 32 + u];
    }
    __syncthreads();

    const float* cores1[4] = {core11, core12, core13, core14};

    for (int idx = tid; idx < 800; idx += blockDim.x) {
        int p  = idx / 200;
        int al = (idx / 100) & 1;
        int k  = (idx / RR) % RR;
        int j  = idx % RR;
        const float* core = cores1[p];
        float s = 0.f;
        #pragma unroll
        for (int i = 0; i < RR; i++)
            s += v[2 * p][al][i] * __ldg(&core[(i * RR + k) * RR + j]);
        WP[p][al][k][j] = s;
    }
    __syncthreads();

    for (int idx = tid; idx < 160; idx += blockDim.x) {
        int p = idx / 40;
        int c = (idx / RR) & 3;
        int j = idx % RR;
        int al = c >> 1, be = c & 1;
        float s = 0.f;
        #pragma unroll
        for (int k = 0; k < RR; k++)
            s += v[2 * p + 1][be][k] * WP[p][al][k][j];
        P[p][c][j] = s;
    }
    __syncthreads();

    for (int idx = tid; idx < 800; idx += blockDim.x) {
        int t  = idx / 400;
        int c1 = (idx / 100) & 3;
        int k  = (idx / RR) % RR;
        int j  = idx % RR;
        const float* core = t ? core22 : core21;
        float s = 0.f;
        #pragma unroll
        for (int i = 0; i < RR; i++)
            s += P[2 * t][c1][i] * __ldg(&core[(i * RR + k) * RR + j]);
        W2[t][c1][k][j] = s;
    }
    __syncthreads();

    for (int idx = tid; idx < 320; idx += blockDim.x) {
        int t = idx / 160;
        int a = (idx / RR) % 16;
        int j = idx % RR;
        int c1 = a >> 2, c2 = a & 3;
        float s = 0.f;
        #pragma unroll
        for (int k = 0; k < RR; k++)
            s += P[2 * t + 1][c2][k] * W2[t][c1][k][j];
        Q[t][a][j] = s;
    }
    __syncthreads();

    for (int idx = tid; idx < 160; idx += blockDim.x) {
        int a = idx / RR, j = idx % RR;
        float s = 0.f;
        #pragma unroll
        for (int i = 0; i < RR; i++)
            s += Q[0][a][i] * __ldg(&MT[i * RR + j]);
        QT[a][j] = s;
    }
    __syncthreads();

    for (int idx = tid; idx < 256; idx += blockDim.x) {
        int a = idx >> 4, a2 = idx & 15;
        float s = 0.f;
        #pragma unroll
        for (int j = 0; j < RR; j++)
            s += QT[a][j] * Q[1][a2][j];
        Sv[a * 16 + a2] = s;
    }
    __syncthreads();

    // Pack this unit's 64 fragment entries: col u lives at n = u>>3,
    // lanes l = (u&7)*4 + tig; k0 = ks*16 + tig*2; entries {k0,k0+1,k0+8,k0+9}.
    for (int idx = tid; idx < 64; idx += blockDim.x) {
        int ks  = idx >> 2;
        int tig = idx & 3;
        int k0  = ks * 16 + tig * 2;
        int l   = (u & 7) * 4 + tig;
        int e   = ks * 128 + (u >> 3) * 32 + l;

        float sv[4] = {Sv[k0], Sv[k0 + 1], Sv[k0 + 8], Sv[k0 + 9]};
        ull bh = 0, bl = 0;
        #pragma unroll
        for (int t = 0; t < 4; t++) {
            u32 bits = __float_as_uint(sv[t]);
            float hif = __uint_as_float(bits & 0xFFFF0000u);
            __nv_bfloat16 lo = __float2bfloat16(sv[t] - hif);
            bh |= (ull)(bits >> 16) << (16 * t);
            bl |= (ull)(*reinterpret_cast<u16*>(&lo)) << (16 * t);
        }
        ulonglong2 p; p.x = bh; p.y = bl;
        Wpk_g[e] = p;
    }
}

// ---------------------------------------------------------------------------
// Warp-MMA helpers (arch-agnostic: sm_80+ mma.sync)
// ---------------------------------------------------------------------------
__device__ __forceinline__ void mma_bf16(float* d, const u32* a, u32 b0, u32 b1) {
    asm volatile("mma.sync.aligned.m16n8k16.row.col.f32.bf16.bf16.f32 "
                 "{%0,%1,%2,%3}, {%4,%5,%6,%7}, {%8,%9}, {%0,%1,%2,%3};"
                 : "+f"(d[0]), "+f"(d[1]), "+f"(d[2]), "+f"(d[3])
                 : "r"(a[0]), "r"(a[1]), "r"(a[2]), "r"(a[3]), "r"(b0), "r"(b1));
}
__device__ __forceinline__ u32 pack_hi(float z0, float z1) {
    u32 r;
    asm("prmt.b32 %0, %1, %2, 0x7632;"
        : "=r"(r) : "r"(__float_as_uint(z0)), "r"(__float_as_uint(z1)));
    return r;
}
__device__ __forceinline__ u32 pack_lo_rn(float l0, float l1) {
    u32 r;
    asm("cvt.rn.bf16x2.f32 %0, %1, %2;" : "=r"(r) : "f"(l1), "f"(l0));
    return r;
}
__device__ __forceinline__ float trunc_bf(float z) {
    return __uint_as_float(__float_as_uint(z) & 0xFFFF0000u);
}

// ---------------------------------------------------------------------------
// Main kernel: out = z @ W. Static grid (512 blocks x 8 warps, 16-batch warp
// tiles). A-fragments built in registers. Split accumulators: accH for the
// hi*hi term (16-deep chain), accC for both correction terms (32-deep chain).
// B staged with 8 coalesced LDG.128 per thread from the pre-packed table.
// ---------------------------------------------------------------------------
__global__ __launch_bounds__(256, 3) void tree_main(const float* __restrict__ X,
                                                    float* __restrict__ out)
{
    __shared__ __align__(16) ulonglong2 sB[2048];   // 32KB: [ks][n][lane] = {bh, bl}

    const int tid  = threadIdx.x;
    const int wid  = tid >> 5;
    const int lane = tid & 31;
    const int g    = lane >> 2;   // fragment row group (0..7)
    const int tig  = lane & 3;    // thread-in-group

    // ---- stage fused B fragments: coalesced vector copy ----
    #pragma unroll
    for (int i = 0; i < 8; i++) {
        int e = tid + i * 256;
        sB[e] = Wpk_g[e];
    }
    __syncthreads();

    const int base_b = (blockIdx.x * 8 + wid) * 16;

    // ---- per-lane monomial factors for its two fragment rows (g, g+8) ----
    float a01r[2][4], a23r[2][4], m2r[2][4];
    #pragma unroll
    for (int r = 0; r < 2; r++) {
        int brow = base_b + g + r * 8;
        const float4* xp = reinterpret_cast<const float4*>(X + (size_t)brow * 16);
        float4 x0 = xp[0], x1 = xp[1], x2 = xp[2], x3 = xp[3];

        a01r[r][0]=x0.x*x0.z; a01r[r][1]=x0.x*x0.w;
        a01r[r][2]=x0.y*x0.z; a01r[r][3]=x0.y*x0.w;
        a23r[r][0]=x1.x*x1.z; a23r[r][1]=x1.x*x1.w;
        a23r[r][2]=x1.y*x1.z; a23r[r][3]=x1.y*x1.w;

        float a45[4], a67[4];
        a45[0]=x2.x*x2.z; a45[1]=x2.x*x2.w; a45[2]=x2.y*x2.z; a45[3]=x2.y*x2.w;
        a67[0]=x3.x*x3.z; a67[1]=x3.x*x3.w; a67[2]=x3.y*x3.z; a67[3]=x3.y*x3.w;

        #pragma unroll
        for (int j = 0; j < 4; j++) {
            int a2 = 2 * tig + (j >> 1) * 8 + (j & 1);
            m2r[r][j] = a45[a2 >> 2] * a67[a2 & 3];
        }
    }

    float accH[4][4], accC[4][4];
    #pragma unroll
    for (int n = 0; n < 4; n++)
        #pragma unroll
        for (int i = 0; i < 4; i++) { accH[n][i] = 0.f; accC[n][i] = 0.f; }

    // ---- 16 K-chunks (each = one 'a' index) ----
    #pragma unroll
    for (int ks = 0; ks < 16; ks++) {
        float m10 = a01r[0][ks >> 2] * a23r[0][ks & 3];
        float m11 = a01r[1][ks >> 2] * a23r[1][ks & 3];

        float z00 = m10 * m2r[0][0], z01 = m10 * m2r[0][1];
        float z02 = m10 * m2r[0][2], z03 = m10 * m2r[0][3];
        float z10 = m11 * m2r[1][0], z11 = m11 * m2r[1][1];
        float z12 = m11 * m2r[1][2], z13 = m11 * m2r[1][3];

        u32 ah[4], al_[4];
        ah[0] = pack_hi(z00, z01);
        ah[1] = pack_hi(z10, z11);
        ah[2] = pack_hi(z02, z03);
        ah[3] = pack_hi(z12, z13);
        al_[0] = pack_lo_rn(z00 - trunc_bf(z00), z01 - trunc_bf(z01));
        al_[1] = pack_lo_rn(z10 - trunc_bf(z10), z11 - trunc_bf(z11));
        al_[2] = pack_lo_rn(z02 - trunc_bf(z02), z03 - trunc_bf(z03));
        al_[3] = pack_lo_rn(z12 - trunc_bf(z12), z13 - trunc_bf(z13));

        u32 bh0[4], bh1[4], bl0[4], bl1[4];
        #pragma unroll
        for (int n = 0; n < 4; n++) {
            ulonglong2 bp = sB[(ks * 4 + n) * 32 + lane];   // one LDS.128
            bh0[n] = (u32)bp.x; bh1[n] = (u32)(bp.x >> 32);
            bl0[n] = (u32)bp.y; bl1[n] = (u32)(bp.y >> 32);
        }

        // hi term -> accH (chain 16); corrections -> accC (chain 32)
        #pragma unroll
        for (int n = 0; n < 4; n++) mma_bf16(accH[n], ah,  bh0[n], bh1[n]);
        #pragma unroll
        for (int n = 0; n < 4; n++) mma_bf16(accC[n], ah,  bl0[n], bl1[n]);
        #pragma unroll
        for (int n = 0; n < 4; n++) mma_bf16(accC[n], al_, bh0[n], bh1[n]);
    }

    // ---- epilogue: merge accumulators, store D frag ----
    #pragma unroll
    for (int n = 0; n < 4; n++) {
        float2 v0; v0.x = accH[n][0] + accC[n][0]; v0.y = accH[n][1] + accC[n][1];
        float2 v1; v1.x = accH[n][2] + accC[n][2]; v1.y = accH[n][3] + accC[n][3];
        *reinterpret_cast<float2*>(out + (size_t)(base_b + g)     * 32 + n * 8 + tig * 2) = v0;
        *reinterpret_cast<float2*>(out + (size_t)(base_b + g + 8) * 32 + n * 8 + tig * 2) = v1;
    }
}

// ---------------------------------------------------------------------------
extern "C" void kernel_launch(void* const* d_in, const int* in_sizes, int n_in,
                              void* d_out, int out_size)
{
    const float* X   = (const float*)d_in[0];
    const float* c11 = (const float*)d_in[1];
    const float* c12 = (const float*)d_in[2];
    const float* c13 = (const float*)d_in[3];
    const float* c14 = (const float*)d_in[4];
    const float* c21 = (const float*)d_in[5];
    const float* c22 = (const float*)d_in[6];
    const float* FM  = (const float*)d_in[7];
    const float* MT  = (const float*)d_in[8];
    (void)n_in; (void)out_size;

    int B = in_sizes[0] / 16;          // X is [B, 8, 2]
    int nblocks = B / 128;             // 8 warps x 16 batches per block

    precompute_S<<<32, 256>>>(c11, c12, c13, c14, c21, c22, FM, MT);
    tree_main<<<nblocks, 256>>>(X, (float*)d_out);
}

// round 13
// speedup vs baseline: 1.4382x; 1.3407x over previous
#include <cuda_runtime.h>
#include <cuda_bf16.h>
#include <cstdint>

typedef unsigned long long ull;
typedef unsigned int       u32;
typedef unsigned short     u16;

#define RR 10

// Pre-packed fused B fragments: e = ks*128 + n*32 + lane -> {bh, bl}
__device__ __align__(16) ulonglong2 Wpk_g[2048];

// ---------------------------------------------------------------------------
// Precompute kernel: one block per unit u. All constant tensors staged to smem
// in ONE coalesced phase, then 6 contraction phases run entirely from smem.
// ---------------------------------------------------------------------------
__global__ void precompute_S(const float* __restrict__ core11,
                             const float* __restrict__ core12,
                             const float* __restrict__ core13,
                             const float* __restrict__ core14,
                             const float* __restrict__ core21,
                             const float* __restrict__ core22,
                             const float* __restrict__ FM,   // [2][10][8][32]
                             const float* __restrict__ MT)   // [10][10]
{
    __shared__ float sC[6][RR * RR * RR];   // all six cores, 24KB
    __shared__ float sMT[RR * RR];
    __shared__ float v[8][2][RR];
    __shared__ float WP[4][2][RR][RR];
    __shared__ float P[4][4][RR];
    __shared__ float W2[2][4][RR][RR];
    __shared__ float Q[2][16][RR];
    __shared__ float QT[16][RR];
    __shared__ float Sv[256];

    const int u = blockIdx.x;
    const int tid = threadIdx.x;

    // ---- single coalesced staging phase ----
    {
        const float* srcs[6] = {core11, core12, core13, core14, core21, core22};
        #pragma unroll
        for (int c = 0; c < 6; c++)
            for (int i = tid; i < RR * RR * RR; i += blockDim.x)
                sC[c][i] = __ldg(&srcs[c][i]);
        for (int i = tid; i < RR * RR; i += blockDim.x)
            sMT[i] = __ldg(&MT[i]);
        for (int idx = tid; idx < 8 * 2 * RR; idx += blockDim.x) {
            int f = idx / (2 * RR);
            int d = (idx / RR) & 1;
            int r = idx % RR;
            v[f][d][r] = __ldg(&FM[((d * RR + r) * 8 + f) * 32 + u]);
        }
    }
    __syncthreads();

    for (int idx = tid; idx < 800; idx += blockDim.x) {
        int p  = idx / 200;
        int al = (idx / 100) & 1;
        int k  = (idx / RR) % RR;
        int j  = idx % RR;
        float s = 0.f;
        #pragma unroll
        for (int i = 0; i < RR; i++)
            s += v[2 * p][al][i] * sC[p][(i * RR + k) * RR + j];
        WP[p][al][k][j] = s;
    }
    __syncthreads();

    for (int idx = tid; idx < 160; idx += blockDim.x) {
        int p = idx / 40;
        int c = (idx / RR) & 3;
        int j = idx % RR;
        int al = c >> 1, be = c & 1;
        float s = 0.f;
        #pragma unroll
        for (int k = 0; k < RR; k++)
            s += v[2 * p + 1][be][k] * WP[p][al][k][j];
        P[p][c][j] = s;
    }
    __syncthreads();

    for (int idx = tid; idx < 800; idx += blockDim.x) {
        int t  = idx / 400;
        int c1 = (idx / 100) & 3;
        int k  = (idx / RR) % RR;
        int j  = idx % RR;
        const float* core = sC[4 + t];
        float s = 0.f;
        #pragma unroll
        for (int i = 0; i < RR; i++)
            s += P[2 * t][c1][i] * core[(i * RR + k) * RR + j];
        W2[t][c1][k][j] = s;
    }
    __syncthreads();

    for (int idx = tid; idx < 320; idx += blockDim.x) {
        int t = idx / 160;
        int a = (idx / RR) % 16;
        int j = idx % RR;
        int c1 = a >> 2, c2 = a & 3;
        float s = 0.f;
        #pragma unroll
        for (int k = 0; k < RR; k++)
            s += P[2 * t + 1][c2][k] * W2[t][c1][k][j];
        Q[t][a][j] = s;
    }
    __syncthreads();

    for (int idx = tid; idx < 160; idx += blockDim.x) {
        int a = idx / RR, j = idx % RR;
        float s = 0.f;
        #pragma unroll
        for (int i = 0; i < RR; i++)
            s += Q[0][a][i] * sMT[i * RR + j];
        QT[a][j] = s;
    }
    __syncthreads();

    for (int idx = tid; idx < 256; idx += blockDim.x) {
        int a = idx >> 4, a2 = idx & 15;
        float s = 0.f;
        #pragma unroll
        for (int j = 0; j < RR; j++)
            s += QT[a][j] * Q[1][a2][j];
        Sv[a * 16 + a2] = s;
    }
    __syncthreads();

    // Pack this unit's 64 fragment entries: col u lives at n = u>>3,
    // lanes l = (u&7)*4 + tig; k0 = ks*16 + tig*2; entries {k0,k0+1,k0+8,k0+9}.
    for (int idx = tid; idx < 64; idx += blockDim.x) {
        int ks  = idx >> 2;
        int tig = idx & 3;
        int k0  = ks * 16 + tig * 2;
        int l   = (u & 7) * 4 + tig;
        int e   = ks * 128 + (u >> 3) * 32 + l;

        float sv[4] = {Sv[k0], Sv[k0 + 1], Sv[k0 + 8], Sv[k0 + 9]};
        ull bh = 0, bl = 0;
        #pragma unroll
        for (int t = 0; t < 4; t++) {
            u32 bits = __float_as_uint(sv[t]);
            float hif = __uint_as_float(bits & 0xFFFF0000u);
            __nv_bfloat16 lo = __float2bfloat16(sv[t] - hif);
            bh |= (ull)(bits >> 16) << (16 * t);
            bl |= (ull)(*reinterpret_cast<u16*>(&lo)) << (16 * t);
        }
        ulonglong2 p; p.x = bh; p.y = bl;
        Wpk_g[e] = p;
    }
}

// ---------------------------------------------------------------------------
// Warp-MMA helpers (arch-agnostic: sm_80+ mma.sync)
// ---------------------------------------------------------------------------
__device__ __forceinline__ void mma_bf16(float* d, const u32* a, u32 b0, u32 b1) {
    asm volatile("mma.sync.aligned.m16n8k16.row.col.f32.bf16.bf16.f32 "
                 "{%0,%1,%2,%3}, {%4,%5,%6,%7}, {%8,%9}, {%0,%1,%2,%3};"
                 : "+f"(d[0]), "+f"(d[1]), "+f"(d[2]), "+f"(d[3])
                 : "r"(a[0]), "r"(a[1]), "r"(a[2]), "r"(a[3]), "r"(b0), "r"(b1));
}
__device__ __forceinline__ u32 pack_hi(float z0, float z1) {
    u32 r;
    asm("prmt.b32 %0, %1, %2, 0x7632;"
        : "=r"(r) : "r"(__float_as_uint(z0)), "r"(__float_as_uint(z1)));
    return r;
}
__device__ __forceinline__ u32 pack_lo_rn(float l0, float l1) {
    u32 r;
    asm("cvt.rn.bf16x2.f32 %0, %1, %2;" : "=r"(r) : "f"(l1), "f"(l0));
    return r;
}
__device__ __forceinline__ float trunc_bf(float z) {
    return __uint_as_float(__float_as_uint(z) & 0xFFFF0000u);
}

// ---------------------------------------------------------------------------
// Main kernel: out = z @ W. Static grid (512 blocks x 8 warps, 16-batch warp
// tiles). A-fragments built in registers; single accumulator set (reg-lean so
// ptxas can software-pipeline the z-build across ks). B staged with 8
// coalesced LDG.128 per thread from the pre-packed table.
// ---------------------------------------------------------------------------
__global__ __launch_bounds__(256, 3) void tree_main(const float* __restrict__ X,
                                                    float* __restrict__ out)
{
    __shared__ __align__(16) ulonglong2 sB[2048];   // 32KB: [ks][n][lane] = {bh, bl}

    const int tid  = threadIdx.x;
    const int wid  = tid >> 5;
    const int lane = tid & 31;
    const int g    = lane >> 2;   // fragment row group (0..7)
    const int tig  = lane & 3;    // thread-in-group

    // ---- stage fused B fragments: coalesced vector copy ----
    #pragma unroll
    for (int i = 0; i < 8; i++) {
        int e = tid + i * 256;
        sB[e] = Wpk_g[e];
    }
    __syncthreads();

    const int base_b = (blockIdx.x * 8 + wid) * 16;

    // ---- per-lane monomial factors for its two fragment rows (g, g+8) ----
    float a01r[2][4], a23r[2][4], m2r[2][4];
    #pragma unroll
    for (int r = 0; r < 2; r++) {
        int brow = base_b + g + r * 8;
        const float4* xp = reinterpret_cast<const float4*>(X + (size_t)brow * 16);
        float4 x0 = xp[0], x1 = xp[1], x2 = xp[2], x3 = xp[3];

        a01r[r][0]=x0.x*x0.z; a01r[r][1]=x0.x*x0.w;
        a01r[r][2]=x0.y*x0.z; a01r[r][3]=x0.y*x0.w;
        a23r[r][0]=x1.x*x1.z; a23r[r][1]=x1.x*x1.w;
        a23r[r][2]=x1.y*x1.z; a23r[r][3]=x1.y*x1.w;

        float a45[4], a67[4];
        a45[0]=x2.x*x2.z; a45[1]=x2.x*x2.w; a45[2]=x2.y*x2.z; a45[3]=x2.y*x2.w;
        a67[0]=x3.x*x3.z; a67[1]=x3.x*x3.w; a67[2]=x3.y*x3.z; a67[3]=x3.y*x3.w;

        #pragma unroll
        for (int j = 0; j < 4; j++) {
            int a2 = 2 * tig + (j >> 1) * 8 + (j & 1);
            m2r[r][j] = a45[a2 >> 2] * a67[a2 & 3];
        }
    }

    float acc[4][4];
    #pragma unroll
    for (int n = 0; n < 4; n++)
        #pragma unroll
        for (int i = 0; i < 4; i++) acc[n][i] = 0.f;

    // ---- 16 K-chunks (each = one 'a' index) ----
    #pragma unroll
    for (int ks = 0; ks < 16; ks++) {
        float m10 = a01r[0][ks >> 2] * a23r[0][ks & 3];
        float m11 = a01r[1][ks >> 2] * a23r[1][ks & 3];

        float z00 = m10 * m2r[0][0], z01 = m10 * m2r[0][1];
        float z02 = m10 * m2r[0][2], z03 = m10 * m2r[0][3];
        float z10 = m11 * m2r[1][0], z11 = m11 * m2r[1][1];
        float z12 = m11 * m2r[1][2], z13 = m11 * m2r[1][3];

        u32 ah[4], al_[4];
        ah[0] = pack_hi(z00, z01);
        ah[1] = pack_hi(z10, z11);
        ah[2] = pack_hi(z02, z03);
        ah[3] = pack_hi(z12, z13);
        al_[0] = pack_lo_rn(z00 - trunc_bf(z00), z01 - trunc_bf(z01));
        al_[1] = pack_lo_rn(z10 - trunc_bf(z10), z11 - trunc_bf(z11));
        al_[2] = pack_lo_rn(z02 - trunc_bf(z02), z03 - trunc_bf(z03));
        al_[3] = pack_lo_rn(z12 - trunc_bf(z12), z13 - trunc_bf(z13));

        u32 bh0[4], bh1[4], bl0[4], bl1[4];
        #pragma unroll
        for (int n = 0; n < 4; n++) {
            ulonglong2 bp = sB[(ks * 4 + n) * 32 + lane];   // one LDS.128
            bh0[n] = (u32)bp.x; bh1[n] = (u32)(bp.x >> 32);
            bl0[n] = (u32)bp.y; bl1[n] = (u32)(bp.y >> 32);
        }

        // term-major: same-acc HMMA spacing ~1 full ks iteration
        #pragma unroll
        for (int n = 0; n < 4; n++) mma_bf16(acc[n], ah,  bh0[n], bh1[n]);
        #pragma unroll
        for (int n = 0; n < 4; n++) mma_bf16(acc[n], ah,  bl0[n], bl1[n]);
        #pragma unroll
        for (int n = 0; n < 4; n++) mma_bf16(acc[n], al_, bh0[n], bh1[n]);
    }

    // ---- epilogue: store D frag rows g/g+8, cols n*8 + tig*2, +1 ----
    #pragma unroll
    for (int n = 0; n < 4; n++) {
        float2 v0; v0.x = acc[n][0]; v0.y = acc[n][1];
        float2 v1; v1.x = acc[n][2]; v1.y = acc[n][3];
        *reinterpret_cast<float2*>(out + (size_t)(base_b + g)     * 32 + n * 8 + tig * 2) = v0;
        *reinterpret_cast<float2*>(out + (size_t)(base_b + g + 8) * 32 + n * 8 + tig * 2) = v1;
    }
}

// ---------------------------------------------------------------------------
extern "C" void kernel_launch(void* const* d_in, const int* in_sizes, int n_in,
                              void* d_out, int out_size)
{
    const float* X   = (const float*)d_in[0];
    const float* c11 = (const float*)d_in[1];
    const float* c12 = (const float*)d_in[2];
    const float* c13 = (const float*)d_in[3];
    const float* c14 = (const float*)d_in[4];
    const float* c21 = (const float*)d_in[5];
    const float* c22 = (const float*)d_in[6];
    const float* FM  = (const float*)d_in[7];
    const float* MT  = (const float*)d_in[8];
    (void)n_in; (void)out_size;

    int B = in_sizes[0] / 16;          // X is [B, 8, 2]
    int nblocks = B / 128;             // 8 warps x 16 batches per block

    precompute_S<<<32, 256>>>(c11, c12, c13, c14, c21, c22, FM, MT);
    tree_main<<<nblocks, 256>>>(X, (float*)d_out);
}